// round 12
// baseline (speedup 1.0000x reference)
#include <cuda_runtime.h>
#include <cuda_fp16.h>
#include <cstdint>

#define NN 50000
#define NNPAD 50048           // 782 * 64
#define NE 800000
#define NG 128
#define FE 16
#define DD 64
#define NBLK ((NN + 255) / 256)   // 196 scan blocks

// ---------------- scratch (static device globals; no allocation) ----------------
__device__ int    d_counts[NN];          // starts 0; re-zeroed by scan_kernel each run
__device__ int    d_offsets[NN + 1];
__device__ int    d_rank[NE];
__device__ unsigned long long d_scanstate[NBLK];  // starts 0; re-zeroed by scatter_kernel
__device__ int2   d_se[NE];              // (src, eid) per CSR slot (sorted by dst)
__device__ __half d_ef16[NE * FE];       // edge features in EDGE order, fp16 (converted in hist)
__device__ float  d_agg16[NNPAD * FE];
__device__ __half d_msg[NNPAD * DD];
__device__ __half d_hA[NNPAD * DD];
__device__ __half d_hB[NNPAD * DD];
__device__ __half d_Wni[80 * 64];        // rows 0-63: W_n2l, rows 64-79: W_e2l
__device__ __half d_Wc16[3 * 64 * 64];
__device__ __half d_Wf16[64 * 64];

__device__ __forceinline__ uint32_t smem_u32(const void* p) {
    return (uint32_t)__cvta_generic_to_shared(p);
}

__device__ __forceinline__ uint32_t h2u(__half2 h) {
    return *reinterpret_cast<uint32_t*>(&h);
}

// ---------------- K1: histogram (rank trick) + ef->fp16 edge-order + weight conversion ----------------
__global__ void hist_kernel(const int* __restrict__ dst, const float* __restrict__ ef,
                            const float* __restrict__ Wn, const float* __restrict__ We,
                            const float* __restrict__ Wc, const float* __restrict__ Wf) {
    int e = blockIdx.x * blockDim.x + threadIdx.x;
    if (e < NE) {
        d_rank[e] = atomicAdd(&d_counts[dst[e]], 1);
        // coalesced fp32 read, coalesced fp16 write (edge order)
        const float4* efr = (const float4*)(ef + e * FE);
        float4 v0 = efr[0], v1 = efr[1], v2 = efr[2], v3 = efr[3];
        uint4 q0 = make_uint4(h2u(__floats2half2_rn(v0.x, v0.y)),
                              h2u(__floats2half2_rn(v0.z, v0.w)),
                              h2u(__floats2half2_rn(v1.x, v1.y)),
                              h2u(__floats2half2_rn(v1.z, v1.w)));
        uint4 q1 = make_uint4(h2u(__floats2half2_rn(v2.x, v2.y)),
                              h2u(__floats2half2_rn(v2.z, v2.w)),
                              h2u(__floats2half2_rn(v3.x, v3.y)),
                              h2u(__floats2half2_rn(v3.z, v3.w)));
        *(uint4*)(d_ef16 + e * FE) = q0;
        *(uint4*)(d_ef16 + e * FE + 8) = q1;
    }
    if (e < 4096) { d_Wni[e] = __float2half(Wn[e]); d_Wf16[e] = __float2half(Wf[e]); }
    else if (e < 5120) d_Wni[e] = __float2half(We[e - 4096]);
    if (e < 12288) d_Wc16[e] = __float2half(Wc[e]);
}

// ---------------- K2: single-pass decoupled-lookback exclusive scan -> offsets; re-zero counts ----------------
__global__ __launch_bounds__(256) void scan_kernel() {
    __shared__ int sm[256];
    __shared__ int s_excl;
    int b = blockIdx.x, t = threadIdx.x;
    int i = b * 256 + t;
    int v = (i < NN) ? d_counts[i] : 0;
    sm[t] = v;
    __syncthreads();
#pragma unroll
    for (int d = 1; d < 256; d <<= 1) {
        int x = (t >= d) ? sm[t - d] : 0;
        __syncthreads();
        sm[t] += x;
        __syncthreads();
    }
    int incl = sm[t];
    int agg = sm[255];
    if (t == 0) {
        unsigned long long fl = (b == 0) ? 2ULL : 1ULL;
        atomicExch(&d_scanstate[b], (fl << 32) | (unsigned long long)(unsigned)agg);
        if (b == 0) s_excl = 0;
    }
    if (b > 0 && t < 32) {
        int lane = t;
        int j = b - 1;
        int excl = 0;
        while (true) {
            int idx = j - lane;
            unsigned long long s;
            if (idx >= 0) {
                do { s = atomicAdd(&d_scanstate[idx], 0ULL); } while ((s >> 32) == 0ULL);
            } else {
                s = (2ULL << 32);
            }
            unsigned fl = (unsigned)(s >> 32);
            int val = (int)(unsigned)(s & 0xffffffffULL);
            unsigned mask = __ballot_sync(0xffffffffu, fl == 2u);
            if (mask) {
                int lmin = __ffs(mask) - 1;
                int contrib = (lane <= lmin) ? val : 0;
#pragma unroll
                for (int o = 16; o > 0; o >>= 1) contrib += __shfl_down_sync(0xffffffffu, contrib, o);
                contrib = __shfl_sync(0xffffffffu, contrib, 0);
                excl += contrib;
                break;
            } else {
                int contrib = val;
#pragma unroll
                for (int o = 16; o > 0; o >>= 1) contrib += __shfl_down_sync(0xffffffffu, contrib, o);
                contrib = __shfl_sync(0xffffffffu, contrib, 0);
                excl += contrib;
                j -= 32;
            }
        }
        if (lane == 0) {
            atomicExch(&d_scanstate[b], (2ULL << 32) | (unsigned long long)(unsigned)(excl + agg));
            s_excl = excl;
        }
    }
    __syncthreads();
    if (i < NN) {
        d_offsets[i] = s_excl + incl - v;
        d_counts[i] = 0;          // restore invariant for next graph replay
    }
    if (b == NBLK - 1 && t == 0) d_offsets[NN] = NE;
}

// ---------------- K3: scatter edge ids into CSR order (atomic-free, no ef traffic) ----------------
__global__ void scatter_kernel(const int* __restrict__ src, const int* __restrict__ dst) {
    int e = blockIdx.x * blockDim.x + threadIdx.x;
    if (e < NE) {
        int dn = dst[e];
        int p = d_offsets[dn] + d_rank[e];
        d_se[p] = make_int2(src[e], e);
    }
    if (e < NBLK) d_scanstate[e] = 0ULL;   // restore invariant
}

// ---------------- K4a: per-node sum of incident edge features (CSR walk, L2-random fp16 reads) ----------------
// warp per node; 8 lanes per edge (half2 granularity), 4 edges in flight per warp.
__global__ __launch_bounds__(256) void agg_edge_kernel() {
    int node = blockIdx.x * 8 + (threadIdx.x >> 5);
    if (node >= NN) return;
    int lane = threadIdx.x & 31;
    int f2 = lane & 7;        // half2 index within row (0..7)
    int eg = lane >> 3;       // edge subgroup (0..3)
    int s = d_offsets[node], e = d_offsets[node + 1];
    const __half2* __restrict__ pf = (const __half2*)d_ef16;
    float2 acc = make_float2(0.f, 0.f);
    for (int base = s; base < e; base += 4) {
        int p = base + eg;
        if (p < e) {
            int eid = d_se[p].y;                 // broadcast within 8-lane subgroup
            float2 fv = __half22float2(pf[eid * 8 + f2]);
            acc.x += fv.x;
            acc.y += fv.y;
        }
    }
    // reduce across the 4 edge subgroups (lanes differing in bits 3,4)
    acc.x += __shfl_xor_sync(0xffffffffu, acc.x, 8);
    acc.y += __shfl_xor_sync(0xffffffffu, acc.y, 8);
    acc.x += __shfl_xor_sync(0xffffffffu, acc.x, 16);
    acc.y += __shfl_xor_sync(0xffffffffu, acc.y, 16);
    if (lane < 8) *(float2*)(d_agg16 + node * FE + f2 * 2) = acc;
}

// ---------------- K4b: init via HMMA: msg = [nf|agg16] @ [Wn;We] + bn + deg*be ; h0 = relu ----------------
__global__ __launch_bounds__(128) void init_mma_kernel(
    const float* __restrict__ nf, const float* __restrict__ bn, const float* __restrict__ be) {
    __shared__ __half sX[64 * 88];   // 64 rows x 80 cols (stride 88)
    __shared__ __half sW[80 * 88];
    int t = threadIdx.x;
    int blockRow = blockIdx.x * 64;
    for (int idx = t; idx < 64 * 32; idx += 128) {
        int row = idx >> 5, c2 = idx & 31;
        int grow = blockRow + row;
        float2 v = (grow < NN) ? *(const float2*)(nf + grow * 64 + c2 * 2) : make_float2(0.f, 0.f);
        *(__half2*)(sX + row * 88 + c2 * 2) = __floats2half2_rn(v.x, v.y);
    }
    for (int idx = t; idx < 64 * 8; idx += 128) {
        int row = idx >> 3, c2 = idx & 7;
        int grow = blockRow + row;
        float2 v = (grow < NN) ? *(const float2*)(d_agg16 + grow * 16 + c2 * 2) : make_float2(0.f, 0.f);
        *(__half2*)(sX + row * 88 + 64 + c2 * 2) = __floats2half2_rn(v.x, v.y);
    }
    for (int idx = t; idx < 80 * 8; idx += 128) {
        int row = idx >> 3, ch = idx & 7;
        int4 v = *(const int4*)(d_Wni + row * 64 + ch * 8);
        *(int4*)(sW + row * 88 + ch * 8) = v;
    }
    __syncthreads();
    int w = t >> 5, lane = t & 31;
    uint32_t a[5][4];
#pragma unroll
    for (int kk = 0; kk < 5; kk++) {
        uint32_t addr = smem_u32(sX + (w * 16 + (lane & 15)) * 88 + kk * 16 + (lane >> 4) * 8);
        asm volatile("ldmatrix.sync.aligned.m8n8.x4.shared.b16 {%0,%1,%2,%3}, [%4];"
            : "=r"(a[kk][0]), "=r"(a[kk][1]), "=r"(a[kk][2]), "=r"(a[kk][3]) : "r"(addr));
    }
    __half2* msg2 = (__half2*)d_msg;
    __half2* h2 = (__half2*)d_hA;
#pragma unroll
    for (int n = 0; n < 8; n++) {
        float c0 = 0.f, c1 = 0.f, c2 = 0.f, c3 = 0.f;
#pragma unroll
        for (int kk = 0; kk < 5; kk++) {
            uint32_t b0, b1;
            uint32_t addr = smem_u32(sW + (kk * 16 + (lane & 15)) * 88 + n * 8);
            asm volatile("ldmatrix.sync.aligned.m8n8.x2.trans.shared.b16 {%0,%1}, [%2];"
                : "=r"(b0), "=r"(b1) : "r"(addr));
            asm volatile("mma.sync.aligned.m16n8k16.row.col.f32.f16.f16.f32 "
                "{%0,%1,%2,%3}, {%4,%5,%6,%7}, {%8,%9}, {%0,%1,%2,%3};"
                : "+f"(c0), "+f"(c1), "+f"(c2), "+f"(c3)
                : "r"(a[kk][0]), "r"(a[kk][1]), "r"(a[kk][2]), "r"(a[kk][3]), "r"(b0), "r"(b1));
        }
        int r0 = blockRow + w * 16 + (lane >> 2);
        int r1 = r0 + 8;
        int col = n * 8 + (lane & 3) * 2;
        float2 bnv = *(const float2*)(bn + col);
        float2 bev = *(const float2*)(be + col);
        float deg0 = (r0 < NN) ? (float)(d_offsets[r0 + 1] - d_offsets[r0]) : 0.f;
        float deg1 = (r1 < NN) ? (float)(d_offsets[r1 + 1] - d_offsets[r1]) : 0.f;
        float m00 = c0 + bnv.x + deg0 * bev.x;
        float m01 = c1 + bnv.y + deg0 * bev.y;
        float m10 = c2 + bnv.x + deg1 * bev.x;
        float m11 = c3 + bnv.y + deg1 * bev.y;
        msg2[r0 * 32 + (col >> 1)] = __floats2half2_rn(m00, m01);
        msg2[r1 * 32 + (col >> 1)] = __floats2half2_rn(m10, m11);
        h2[r0 * 32 + (col >> 1)] = __floats2half2_rn(fmaxf(m00, 0.f), fmaxf(m01, 0.f));
        h2[r1 * 32 + (col >> 1)] = __floats2half2_rn(fmaxf(m10, 0.f), fmaxf(m11, 0.f));
    }
}

// ---------------- K6: fused gather+GEMM (+ final GEMM & graph-pool on lv2) ----------------
// 512 threads = 16 warps = 16 nodes per block. 50000 = 3125 * 16 exactly.
__global__ __launch_bounds__(512) void gather_mma_kernel(
    const __half* __restrict__ W16, const float* __restrict__ bc, int lv,
    const float* __restrict__ bf, const int* __restrict__ gid, float* __restrict__ out) {
    __shared__ __half sW[64 * 72];
    __shared__ __half sWf[64 * 72];
    __shared__ __half sPool[16 * 72];
    __shared__ __half sH3[16 * 72];
    __shared__ float sOut[16 * 66];
    int t = threadIdx.x;
    int warp = t >> 5, lane = t & 31;
    // zero the output accumulator during lv1 (kernel-boundary-ordered before lv2's atomics)
    if (lv == 1) {
        int gtid = blockIdx.x * 512 + t;
        if (gtid < NG * DD) out[gtid] = 0.f;
    }
    {
        int row = t >> 3, ch = t & 7;
        if (t < 512) {
            *(int4*)(sW + row * 72 + ch * 8) = *(const int4*)(W16 + row * 64 + ch * 8);
            if (lv == 2)
                *(int4*)(sWf + row * 72 + ch * 8) = *(const int4*)(d_Wf16 + row * 64 + ch * 8);
        }
    }
    const __half2* __restrict__ hin = (lv & 1) ? (const __half2*)d_hB : (const __half2*)d_hA;
    __half2* __restrict__ hout = (lv & 1) ? (__half2*)d_hA : (__half2*)d_hB;

    int node = blockIdx.x * 16 + warp;
    int s = d_offsets[node], e = d_offsets[node + 1];
    float2 acc0 = make_float2(0.f, 0.f), acc1 = make_float2(0.f, 0.f);
    float2 acc2 = make_float2(0.f, 0.f), acc3 = make_float2(0.f, 0.f);
    int p = s;
    for (; p + 4 <= e; p += 4) {
        int i0 = d_se[p].x, i1 = d_se[p + 1].x, i2 = d_se[p + 2].x, i3 = d_se[p + 3].x;
        float2 f0 = __half22float2(hin[i0 * 32 + lane]);
        float2 f1 = __half22float2(hin[i1 * 32 + lane]);
        float2 f2 = __half22float2(hin[i2 * 32 + lane]);
        float2 f3 = __half22float2(hin[i3 * 32 + lane]);
        acc0.x += f0.x; acc0.y += f0.y;
        acc1.x += f1.x; acc1.y += f1.y;
        acc2.x += f2.x; acc2.y += f2.y;
        acc3.x += f3.x; acc3.y += f3.y;
    }
    for (; p < e; p++) {
        float2 f = __half22float2(hin[d_se[p].x * 32 + lane]);
        acc0.x += f.x; acc0.y += f.y;
    }
    float x0 = (acc0.x + acc1.x) + (acc2.x + acc3.x);
    float x1 = (acc0.y + acc1.y) + (acc2.y + acc3.y);
    *(__half2*)(sPool + warp * 72 + 2 * lane) = __floats2half2_rn(x0, x1);
    __syncthreads();

    if (warp < 8) {
        float c0 = 0.f, c1 = 0.f, c2 = 0.f, c3 = 0.f;
#pragma unroll
        for (int kk = 0; kk < 4; kk++) {
            uint32_t a0, a1, a2, a3;
            uint32_t addrA = smem_u32(sPool + (lane & 15) * 72 + kk * 16 + (lane >> 4) * 8);
            asm volatile("ldmatrix.sync.aligned.m8n8.x4.shared.b16 {%0,%1,%2,%3}, [%4];"
                : "=r"(a0), "=r"(a1), "=r"(a2), "=r"(a3) : "r"(addrA));
            uint32_t b0, b1;
            uint32_t addrB = smem_u32(sW + (kk * 16 + (lane & 15)) * 72 + warp * 8);
            asm volatile("ldmatrix.sync.aligned.m8n8.x2.trans.shared.b16 {%0,%1}, [%2];"
                : "=r"(b0), "=r"(b1) : "r"(addrB));
            asm volatile("mma.sync.aligned.m16n8k16.row.col.f32.f16.f16.f32 "
                "{%0,%1,%2,%3}, {%4,%5,%6,%7}, {%8,%9}, {%0,%1,%2,%3};"
                : "+f"(c0), "+f"(c1), "+f"(c2), "+f"(c3)
                : "r"(a0), "r"(a1), "r"(a2), "r"(a3), "r"(b0), "r"(b1));
        }
        int r0 = lane >> 2;
        int col = warp * 8 + (lane & 3) * 2;
        int n0 = blockIdx.x * 16 + r0;
        int n1 = n0 + 8;
        float2 bv = *(const float2*)(bc + col);
        float2 m0 = __half22float2(((const __half2*)d_msg)[n0 * 32 + (col >> 1)]);
        float2 m1 = __half22float2(((const __half2*)d_msg)[n1 * 32 + (col >> 1)]);
        float o00 = fmaxf(c0 + bv.x + m0.x, 0.f);
        float o01 = fmaxf(c1 + bv.y + m0.y, 0.f);
        float o10 = fmaxf(c2 + bv.x + m1.x, 0.f);
        float o11 = fmaxf(c3 + bv.y + m1.y, 0.f);
        if (lv != 2) {
            hout[n0 * 32 + (col >> 1)] = __floats2half2_rn(o00, o01);
            hout[n1 * 32 + (col >> 1)] = __floats2half2_rn(o10, o11);
        } else {
            *(__half2*)(sH3 + r0 * 72 + col) = __floats2half2_rn(o00, o01);
            *(__half2*)(sH3 + (r0 + 8) * 72 + col) = __floats2half2_rn(o10, o11);
        }
    }
    if (lv == 2) {
        __syncthreads();
        // second MMA: y = relu(h3 @ Wf + bf), 16x64 tile
        if (warp < 8) {
            float c0 = 0.f, c1 = 0.f, c2 = 0.f, c3 = 0.f;
#pragma unroll
            for (int kk = 0; kk < 4; kk++) {
                uint32_t a0, a1, a2, a3;
                uint32_t addrA = smem_u32(sH3 + (lane & 15) * 72 + kk * 16 + (lane >> 4) * 8);
                asm volatile("ldmatrix.sync.aligned.m8n8.x4.shared.b16 {%0,%1,%2,%3}, [%4];"
                    : "=r"(a0), "=r"(a1), "=r"(a2), "=r"(a3) : "r"(addrA));
                uint32_t b0, b1;
                uint32_t addrB = smem_u32(sWf + (kk * 16 + (lane & 15)) * 72 + warp * 8);
                asm volatile("ldmatrix.sync.aligned.m8n8.x2.trans.shared.b16 {%0,%1}, [%2];"
                    : "=r"(b0), "=r"(b1) : "r"(addrB));
                asm volatile("mma.sync.aligned.m16n8k16.row.col.f32.f16.f16.f32 "
                    "{%0,%1,%2,%3}, {%4,%5,%6,%7}, {%8,%9}, {%0,%1,%2,%3};"
                    : "+f"(c0), "+f"(c1), "+f"(c2), "+f"(c3)
                    : "r"(a0), "r"(a1), "r"(a2), "r"(a3), "r"(b0), "r"(b1));
            }
            int r0 = lane >> 2;
            int col = warp * 8 + (lane & 3) * 2;
            float2 bv = *(const float2*)(bf + col);
            sOut[r0 * 66 + col]           = fmaxf(c0 + bv.x, 0.f);
            sOut[r0 * 66 + col + 1]       = fmaxf(c1 + bv.y, 0.f);
            sOut[(r0 + 8) * 66 + col]     = fmaxf(c2 + bv.x, 0.f);
            sOut[(r0 + 8) * 66 + col + 1] = fmaxf(c3 + bv.y, 0.f);
        }
        __syncthreads();
        // graph pooling of this block's 16 rows
        if (warp < 2) {
            int colbase = warp * 32 + lane;
            int n0 = blockIdx.x * 16;
            int gv = gid[n0 + (lane & 15)];
            int g0 = __shfl_sync(0xffffffffu, gv, 0);
            bool uni = __all_sync(0xffffffffu, gv == g0);
            if (uni) {
                float sAcc = 0.f;
#pragma unroll
                for (int r = 0; r < 16; r++) sAcc += sOut[r * 66 + colbase];
                atomicAdd(&out[g0 * 64 + colbase], sAcc);
            } else {
                for (int r = 0; r < 16; r++)
                    atomicAdd(&out[gid[n0 + r] * 64 + colbase], sOut[r * 66 + colbase]);
            }
        }
    }
}

// ---------------- host ----------------
extern "C" void kernel_launch(void* const* d_in, const int* in_sizes, int n_in,
                              void* d_out, int out_size) {
    const float *nf = 0, *ef = 0, *Wn = 0, *bn = 0, *We = 0, *be = 0;
    const float *Wc = 0, *bc = 0, *Wf = 0, *bf = 0;
    const int *esrc = 0, *edst = 0, *gid = 0;
    int n800 = 0, n4096 = 0, n64 = 0;
    for (int i = 0; i < n_in; i++) {
        int sz = in_sizes[i];
        const void* p = d_in[i];
        if (sz == NN * 64)      nf = (const float*)p;
        else if (sz == NE * 16) ef = (const float*)p;
        else if (sz == NE)      { if (n800++ == 0) esrc = (const int*)p; else edst = (const int*)p; }
        else if (sz == NN)      gid = (const int*)p;
        else if (sz == 4096)    { if (n4096++ == 0) Wn = (const float*)p; else Wf = (const float*)p; }
        else if (sz == 1024)    We = (const float*)p;
        else if (sz == 12288)   Wc = (const float*)p;
        else if (sz == 192)     bc = (const float*)p;
        else if (sz == 64)      { if (n64 == 0) bn = (const float*)p;
                                  else if (n64 == 1) be = (const float*)p;
                                  else bf = (const float*)p; n64++; }
    }
    float* out = (float*)d_out;

    __half* Wc16_ptr;
    cudaGetSymbolAddress((void**)&Wc16_ptr, d_Wc16);

    hist_kernel<<<(NE + 255) / 256, 256>>>(edst, ef, Wn, We, Wc, Wf);
    scan_kernel<<<NBLK, 256>>>();
    scatter_kernel<<<(NE + 255) / 256, 256>>>(esrc, edst);
    agg_edge_kernel<<<(NN + 7) / 8, 256>>>();
    init_mma_kernel<<<NNPAD / 64, 128>>>(nf, bn, be);
    for (int lv = 0; lv < 3; lv++)
        gather_mma_kernel<<<NN / 16, 512>>>(Wc16_ptr + lv * 4096, bc + lv * 64, lv, bf, gid, out);
}

// round 13
// speedup vs baseline: 1.0203x; 1.0203x over previous
#include <cuda_runtime.h>
#include <cuda_fp16.h>
#include <cstdint>

#define NN 50000
#define NNPAD 50048           // 782 * 64
#define NE 800000
#define NG 128
#define FE 16
#define DD 64
#define NBLK ((NN + 255) / 256)   // 196 scan blocks

// ---------------- scratch (static device globals; no allocation) ----------------
__device__ int    d_counts[NN];          // starts 0; re-zeroed by scan_kernel each run
__device__ int    d_offsets[NN + 1];
__device__ int    d_rank[NE];
__device__ unsigned long long d_scanstate[NBLK];  // starts 0; re-zeroed by scatter_kernel
__device__ int    d_src[NE];             // src node per CSR slot (sorted by dst)
__device__ __half d_ef16p[NE * FE];      // edge features permuted into CSR order, fp16
__device__ float  d_agg16[NNPAD * FE];
__device__ __half d_msg[NNPAD * DD];
__device__ __half d_hA[NNPAD * DD];
__device__ __half d_hB[NNPAD * DD];
__device__ __half d_Wni[80 * 64];        // rows 0-63: W_n2l, rows 64-79: W_e2l
__device__ __half d_Wc16[3 * 64 * 64];
__device__ __half d_Wf16[64 * 64];

__device__ __forceinline__ uint32_t smem_u32(const void* p) {
    return (uint32_t)__cvta_generic_to_shared(p);
}

__device__ __forceinline__ uint32_t h2u(__half2 h) {
    return *reinterpret_cast<uint32_t*>(&h);
}

__device__ __forceinline__ void addh2(float2& a, uint32_t u) {
    float2 f = __half22float2(*reinterpret_cast<__half2*>(&u));
    a.x += f.x; a.y += f.y;
}

// ---------------- K1: histogram of edge_dst (rank trick) + fp16 weight conversion ----------------
__global__ void hist_kernel(const int* __restrict__ dst,
                            const float* __restrict__ Wn, const float* __restrict__ We,
                            const float* __restrict__ Wc, const float* __restrict__ Wf) {
    int e = blockIdx.x * blockDim.x + threadIdx.x;
    if (e < NE) d_rank[e] = atomicAdd(&d_counts[dst[e]], 1);
    if (e < 4096) { d_Wni[e] = __float2half(Wn[e]); d_Wf16[e] = __float2half(Wf[e]); }
    else if (e < 5120) d_Wni[e] = __float2half(We[e - 4096]);
    if (e < 12288) d_Wc16[e] = __float2half(Wc[e]);
}

// ---------------- K2: single-pass decoupled-lookback exclusive scan -> offsets; re-zero counts ----------------
__global__ __launch_bounds__(256) void scan_kernel() {
    __shared__ int sm[256];
    __shared__ int s_excl;
    int b = blockIdx.x, t = threadIdx.x;
    int i = b * 256 + t;
    int v = (i < NN) ? d_counts[i] : 0;
    sm[t] = v;
    __syncthreads();
#pragma unroll
    for (int d = 1; d < 256; d <<= 1) {
        int x = (t >= d) ? sm[t - d] : 0;
        __syncthreads();
        sm[t] += x;
        __syncthreads();
    }
    int incl = sm[t];
    int agg = sm[255];
    if (t == 0) {
        unsigned long long fl = (b == 0) ? 2ULL : 1ULL;
        atomicExch(&d_scanstate[b], (fl << 32) | (unsigned long long)(unsigned)agg);
        if (b == 0) s_excl = 0;
    }
    if (b > 0 && t < 32) {
        int lane = t;
        int j = b - 1;
        int excl = 0;
        while (true) {
            int idx = j - lane;
            unsigned long long s;
            if (idx >= 0) {
                do { s = atomicAdd(&d_scanstate[idx], 0ULL); } while ((s >> 32) == 0ULL);
            } else {
                s = (2ULL << 32);
            }
            unsigned fl = (unsigned)(s >> 32);
            int val = (int)(unsigned)(s & 0xffffffffULL);
            unsigned mask = __ballot_sync(0xffffffffu, fl == 2u);
            if (mask) {
                int lmin = __ffs(mask) - 1;
                int contrib = (lane <= lmin) ? val : 0;
#pragma unroll
                for (int o = 16; o > 0; o >>= 1) contrib += __shfl_down_sync(0xffffffffu, contrib, o);
                contrib = __shfl_sync(0xffffffffu, contrib, 0);
                excl += contrib;
                break;
            } else {
                int contrib = val;
#pragma unroll
                for (int o = 16; o > 0; o >>= 1) contrib += __shfl_down_sync(0xffffffffu, contrib, o);
                contrib = __shfl_sync(0xffffffffu, contrib, 0);
                excl += contrib;
                j -= 32;
            }
        }
        if (lane == 0) {
            atomicExch(&d_scanstate[b], (2ULL << 32) | (unsigned long long)(unsigned)(excl + agg));
            s_excl = excl;
        }
    }
    __syncthreads();
    if (i < NN) {
        d_offsets[i] = s_excl + incl - v;
        d_counts[i] = 0;          // restore invariant for next graph replay
    }
    if (b == NBLK - 1 && t == 0) d_offsets[NN] = NE;
}

// ---------------- K3: scatter edges into CSR order + permute edge features to fp16 ----------------
__global__ void scatter_kernel(const int* __restrict__ src, const int* __restrict__ dst,
                               const float* __restrict__ ef) {
    int e = blockIdx.x * blockDim.x + threadIdx.x;
    if (e < NE) {
        int dn = dst[e];
        int p = d_offsets[dn] + d_rank[e];
        d_src[p] = src[e];
        const float4* efr = (const float4*)(ef + e * FE);
        float4 v0 = efr[0], v1 = efr[1], v2 = efr[2], v3 = efr[3];
        uint4 q0 = make_uint4(h2u(__floats2half2_rn(v0.x, v0.y)),
                              h2u(__floats2half2_rn(v0.z, v0.w)),
                              h2u(__floats2half2_rn(v1.x, v1.y)),
                              h2u(__floats2half2_rn(v1.z, v1.w)));
        uint4 q1 = make_uint4(h2u(__floats2half2_rn(v2.x, v2.y)),
                              h2u(__floats2half2_rn(v2.z, v2.w)),
                              h2u(__floats2half2_rn(v3.x, v3.y)),
                              h2u(__floats2half2_rn(v3.z, v3.w)));
        *(uint4*)(d_ef16p + p * FE) = q0;
        *(uint4*)(d_ef16p + p * FE + 8) = q1;
    }
    if (e < NBLK) d_scanstate[e] = 0ULL;   // restore invariant
}

// ---------------- K4a: per-node sum of incident edge features (coalesced CSR walk, 8B/lane) ----------------
// warp per node; 4 lanes per edge (uint2 = 4 halves), 8 edges in flight per warp.
__global__ __launch_bounds__(256) void agg_edge_kernel() {
    int node = blockIdx.x * 8 + (threadIdx.x >> 5);
    if (node >= NN) return;
    int lane = threadIdx.x & 31;
    int f4 = lane & 3;        // 8B chunk within the 32B row (0..3)
    int eg = lane >> 2;       // edge subgroup (0..7)
    int s = d_offsets[node], e = d_offsets[node + 1];
    const uint2* __restrict__ pf = (const uint2*)d_ef16p;  // 4 uint2 per edge row
    float2 acc0 = make_float2(0.f, 0.f), acc1 = make_float2(0.f, 0.f);
    for (int base = s; base < e; base += 8) {
        int p = base + eg;
        if (p < e) {
            uint2 q = pf[p * 4 + f4];
            addh2(acc0, q.x);
            addh2(acc1, q.y);
        }
    }
    // reduce across the 8 edge subgroups (lane bits 2,3,4)
#pragma unroll
    for (int o = 4; o <= 16; o <<= 1) {
        acc0.x += __shfl_xor_sync(0xffffffffu, acc0.x, o);
        acc0.y += __shfl_xor_sync(0xffffffffu, acc0.y, o);
        acc1.x += __shfl_xor_sync(0xffffffffu, acc1.x, o);
        acc1.y += __shfl_xor_sync(0xffffffffu, acc1.y, o);
    }
    if (lane < 4)
        *(float4*)(d_agg16 + node * FE + f4 * 4) = make_float4(acc0.x, acc0.y, acc1.x, acc1.y);
}

// ---------------- K4b: init via HMMA: msg = [nf|agg16] @ [Wn;We] + bn + deg*be ; h0 = relu ----------------
__global__ __launch_bounds__(128) void init_mma_kernel(
    const float* __restrict__ nf, const float* __restrict__ bn, const float* __restrict__ be) {
    __shared__ __half sX[64 * 88];   // 64 rows x 80 cols (stride 88)
    __shared__ __half sW[80 * 88];
    int t = threadIdx.x;
    int blockRow = blockIdx.x * 64;
    for (int idx = t; idx < 64 * 32; idx += 128) {
        int row = idx >> 5, c2 = idx & 31;
        int grow = blockRow + row;
        float2 v = (grow < NN) ? *(const float2*)(nf + grow * 64 + c2 * 2) : make_float2(0.f, 0.f);
        *(__half2*)(sX + row * 88 + c2 * 2) = __floats2half2_rn(v.x, v.y);
    }
    for (int idx = t; idx < 64 * 8; idx += 128) {
        int row = idx >> 3, c2 = idx & 7;
        int grow = blockRow + row;
        float2 v = (grow < NN) ? *(const float2*)(d_agg16 + grow * 16 + c2 * 2) : make_float2(0.f, 0.f);
        *(__half2*)(sX + row * 88 + 64 + c2 * 2) = __floats2half2_rn(v.x, v.y);
    }
    for (int idx = t; idx < 80 * 8; idx += 128) {
        int row = idx >> 3, ch = idx & 7;
        int4 v = *(const int4*)(d_Wni + row * 64 + ch * 8);
        *(int4*)(sW + row * 88 + ch * 8) = v;
    }
    __syncthreads();
    int w = t >> 5, lane = t & 31;
    uint32_t a[5][4];
#pragma unroll
    for (int kk = 0; kk < 5; kk++) {
        uint32_t addr = smem_u32(sX + (w * 16 + (lane & 15)) * 88 + kk * 16 + (lane >> 4) * 8);
        asm volatile("ldmatrix.sync.aligned.m8n8.x4.shared.b16 {%0,%1,%2,%3}, [%4];"
            : "=r"(a[kk][0]), "=r"(a[kk][1]), "=r"(a[kk][2]), "=r"(a[kk][3]) : "r"(addr));
    }
    __half2* msg2 = (__half2*)d_msg;
    __half2* h2 = (__half2*)d_hA;
#pragma unroll
    for (int n = 0; n < 8; n++) {
        float c0 = 0.f, c1 = 0.f, c2 = 0.f, c3 = 0.f;
#pragma unroll
        for (int kk = 0; kk < 5; kk++) {
            uint32_t b0, b1;
            uint32_t addr = smem_u32(sW + (kk * 16 + (lane & 15)) * 88 + n * 8);
            asm volatile("ldmatrix.sync.aligned.m8n8.x2.trans.shared.b16 {%0,%1}, [%2];"
                : "=r"(b0), "=r"(b1) : "r"(addr));
            asm volatile("mma.sync.aligned.m16n8k16.row.col.f32.f16.f16.f32 "
                "{%0,%1,%2,%3}, {%4,%5,%6,%7}, {%8,%9}, {%0,%1,%2,%3};"
                : "+f"(c0), "+f"(c1), "+f"(c2), "+f"(c3)
                : "r"(a[kk][0]), "r"(a[kk][1]), "r"(a[kk][2]), "r"(a[kk][3]), "r"(b0), "r"(b1));
        }
        int r0 = blockRow + w * 16 + (lane >> 2);
        int r1 = r0 + 8;
        int col = n * 8 + (lane & 3) * 2;
        float2 bnv = *(const float2*)(bn + col);
        float2 bev = *(const float2*)(be + col);
        float deg0 = (r0 < NN) ? (float)(d_offsets[r0 + 1] - d_offsets[r0]) : 0.f;
        float deg1 = (r1 < NN) ? (float)(d_offsets[r1 + 1] - d_offsets[r1]) : 0.f;
        float m00 = c0 + bnv.x + deg0 * bev.x;
        float m01 = c1 + bnv.y + deg0 * bev.y;
        float m10 = c2 + bnv.x + deg1 * bev.x;
        float m11 = c3 + bnv.y + deg1 * bev.y;
        msg2[r0 * 32 + (col >> 1)] = __floats2half2_rn(m00, m01);
        msg2[r1 * 32 + (col >> 1)] = __floats2half2_rn(m10, m11);
        h2[r0 * 32 + (col >> 1)] = __floats2half2_rn(fmaxf(m00, 0.f), fmaxf(m01, 0.f));
        h2[r1 * 32 + (col >> 1)] = __floats2half2_rn(fmaxf(m10, 0.f), fmaxf(m11, 0.f));
    }
}

// ---------------- K6: fused gather+GEMM (+ final GEMM & graph-pool on lv2) ----------------
// 512 threads = 16 warps = 16 nodes per block. 50000 = 3125 * 16 exactly.
__global__ __launch_bounds__(512) void gather_mma_kernel(
    const __half* __restrict__ W16, const float* __restrict__ bc, int lv,
    const float* __restrict__ bf, const int* __restrict__ gid, float* __restrict__ out) {
    __shared__ __half sW[64 * 72];
    __shared__ __half sWf[64 * 72];
    __shared__ __half sPool[16 * 72];
    __shared__ __half sH3[16 * 72];
    __shared__ float sOut[16 * 66];
    int t = threadIdx.x;
    int warp = t >> 5, lane = t & 31;
    // zero the output accumulator during lv1 (kernel-boundary-ordered before lv2's atomics)
    if (lv == 1) {
        int gtid = blockIdx.x * 512 + t;
        if (gtid < NG * DD) out[gtid] = 0.f;
    }
    {
        int row = t >> 3, ch = t & 7;
        if (t < 512) {
            *(int4*)(sW + row * 72 + ch * 8) = *(const int4*)(W16 + row * 64 + ch * 8);
            if (lv == 2)
                *(int4*)(sWf + row * 72 + ch * 8) = *(const int4*)(d_Wf16 + row * 64 + ch * 8);
        }
    }
    const __half2* __restrict__ hin = (lv & 1) ? (const __half2*)d_hB : (const __half2*)d_hA;
    __half2* __restrict__ hout = (lv & 1) ? (__half2*)d_hA : (__half2*)d_hB;

    int node = blockIdx.x * 16 + warp;
    int s = d_offsets[node], e = d_offsets[node + 1];
    float2 acc0 = make_float2(0.f, 0.f), acc1 = make_float2(0.f, 0.f);
    float2 acc2 = make_float2(0.f, 0.f), acc3 = make_float2(0.f, 0.f);
    int p = s;
    for (; p + 4 <= e; p += 4) {
        int i0 = d_src[p], i1 = d_src[p + 1], i2 = d_src[p + 2], i3 = d_src[p + 3];
        float2 f0 = __half22float2(hin[i0 * 32 + lane]);
        float2 f1 = __half22float2(hin[i1 * 32 + lane]);
        float2 f2 = __half22float2(hin[i2 * 32 + lane]);
        float2 f3 = __half22float2(hin[i3 * 32 + lane]);
        acc0.x += f0.x; acc0.y += f0.y;
        acc1.x += f1.x; acc1.y += f1.y;
        acc2.x += f2.x; acc2.y += f2.y;
        acc3.x += f3.x; acc3.y += f3.y;
    }
    for (; p < e; p++) {
        float2 f = __half22float2(hin[d_src[p] * 32 + lane]);
        acc0.x += f.x; acc0.y += f.y;
    }
    float x0 = (acc0.x + acc1.x) + (acc2.x + acc3.x);
    float x1 = (acc0.y + acc1.y) + (acc2.y + acc3.y);
    *(__half2*)(sPool + warp * 72 + 2 * lane) = __floats2half2_rn(x0, x1);
    __syncthreads();

    if (warp < 8) {
        float c0 = 0.f, c1 = 0.f, c2 = 0.f, c3 = 0.f;
#pragma unroll
        for (int kk = 0; kk < 4; kk++) {
            uint32_t a0, a1, a2, a3;
            uint32_t addrA = smem_u32(sPool + (lane & 15) * 72 + kk * 16 + (lane >> 4) * 8);
            asm volatile("ldmatrix.sync.aligned.m8n8.x4.shared.b16 {%0,%1,%2,%3}, [%4];"
                : "=r"(a0), "=r"(a1), "=r"(a2), "=r"(a3) : "r"(addrA));
            uint32_t b0, b1;
            uint32_t addrB = smem_u32(sW + (kk * 16 + (lane & 15)) * 72 + warp * 8);
            asm volatile("ldmatrix.sync.aligned.m8n8.x2.trans.shared.b16 {%0,%1}, [%2];"
                : "=r"(b0), "=r"(b1) : "r"(addrB));
            asm volatile("mma.sync.aligned.m16n8k16.row.col.f32.f16.f16.f32 "
                "{%0,%1,%2,%3}, {%4,%5,%6,%7}, {%8,%9}, {%0,%1,%2,%3};"
                : "+f"(c0), "+f"(c1), "+f"(c2), "+f"(c3)
                : "r"(a0), "r"(a1), "r"(a2), "r"(a3), "r"(b0), "r"(b1));
        }
        int r0 = lane >> 2;
        int col = warp * 8 + (lane & 3) * 2;
        int n0 = blockIdx.x * 16 + r0;
        int n1 = n0 + 8;
        float2 bv = *(const float2*)(bc + col);
        float2 m0 = __half22float2(((const __half2*)d_msg)[n0 * 32 + (col >> 1)]);
        float2 m1 = __half22float2(((const __half2*)d_msg)[n1 * 32 + (col >> 1)]);
        float o00 = fmaxf(c0 + bv.x + m0.x, 0.f);
        float o01 = fmaxf(c1 + bv.y + m0.y, 0.f);
        float o10 = fmaxf(c2 + bv.x + m1.x, 0.f);
        float o11 = fmaxf(c3 + bv.y + m1.y, 0.f);
        if (lv != 2) {
            hout[n0 * 32 + (col >> 1)] = __floats2half2_rn(o00, o01);
            hout[n1 * 32 + (col >> 1)] = __floats2half2_rn(o10, o11);
        } else {
            *(__half2*)(sH3 + r0 * 72 + col) = __floats2half2_rn(o00, o01);
            *(__half2*)(sH3 + (r0 + 8) * 72 + col) = __floats2half2_rn(o10, o11);
        }
    }
    if (lv == 2) {
        __syncthreads();
        // second MMA: y = relu(h3 @ Wf + bf), 16x64 tile
        if (warp < 8) {
            float c0 = 0.f, c1 = 0.f, c2 = 0.f, c3 = 0.f;
#pragma unroll
            for (int kk = 0; kk < 4; kk++) {
                uint32_t a0, a1, a2, a3;
                uint32_t addrA = smem_u32(sH3 + (lane & 15) * 72 + kk * 16 + (lane >> 4) * 8);
                asm volatile("ldmatrix.sync.aligned.m8n8.x4.shared.b16 {%0,%1,%2,%3}, [%4];"
                    : "=r"(a0), "=r"(a1), "=r"(a2), "=r"(a3) : "r"(addrA));
                uint32_t b0, b1;
                uint32_t addrB = smem_u32(sWf + (kk * 16 + (lane & 15)) * 72 + warp * 8);
                asm volatile("ldmatrix.sync.aligned.m8n8.x2.trans.shared.b16 {%0,%1}, [%2];"
                    : "=r"(b0), "=r"(b1) : "r"(addrB));
                asm volatile("mma.sync.aligned.m16n8k16.row.col.f32.f16.f16.f32 "
                    "{%0,%1,%2,%3}, {%4,%5,%6,%7}, {%8,%9}, {%0,%1,%2,%3};"
                    : "+f"(c0), "+f"(c1), "+f"(c2), "+f"(c3)
                    : "r"(a0), "r"(a1), "r"(a2), "r"(a3), "r"(b0), "r"(b1));
            }
            int r0 = lane >> 2;
            int col = warp * 8 + (lane & 3) * 2;
            float2 bv = *(const float2*)(bf + col);
            sOut[r0 * 66 + col]           = fmaxf(c0 + bv.x, 0.f);
            sOut[r0 * 66 + col + 1]       = fmaxf(c1 + bv.y, 0.f);
            sOut[(r0 + 8) * 66 + col]     = fmaxf(c2 + bv.x, 0.f);
            sOut[(r0 + 8) * 66 + col + 1] = fmaxf(c3 + bv.y, 0.f);
        }
        __syncthreads();
        // graph pooling of this block's 16 rows
        if (warp < 2) {
            int colbase = warp * 32 + lane;
            int n0 = blockIdx.x * 16;
            int gv = gid[n0 + (lane & 15)];
            int g0 = __shfl_sync(0xffffffffu, gv, 0);
            bool uni = __all_sync(0xffffffffu, gv == g0);
            if (uni) {
                float sAcc = 0.f;
#pragma unroll
                for (int r = 0; r < 16; r++) sAcc += sOut[r * 66 + colbase];
                atomicAdd(&out[g0 * 64 + colbase], sAcc);
            } else {
                for (int r = 0; r < 16; r++)
                    atomicAdd(&out[gid[n0 + r] * 64 + colbase], sOut[r * 66 + colbase]);
            }
        }
    }
}

// ---------------- host ----------------
extern "C" void kernel_launch(void* const* d_in, const int* in_sizes, int n_in,
                              void* d_out, int out_size) {
    const float *nf = 0, *ef = 0, *Wn = 0, *bn = 0, *We = 0, *be = 0;
    const float *Wc = 0, *bc = 0, *Wf = 0, *bf = 0;
    const int *esrc = 0, *edst = 0, *gid = 0;
    int n800 = 0, n4096 = 0, n64 = 0;
    for (int i = 0; i < n_in; i++) {
        int sz = in_sizes[i];
        const void* p = d_in[i];
        if (sz == NN * 64)      nf = (const float*)p;
        else if (sz == NE * 16) ef = (const float*)p;
        else if (sz == NE)      { if (n800++ == 0) esrc = (const int*)p; else edst = (const int*)p; }
        else if (sz == NN)      gid = (const int*)p;
        else if (sz == 4096)    { if (n4096++ == 0) Wn = (const float*)p; else Wf = (const float*)p; }
        else if (sz == 1024)    We = (const float*)p;
        else if (sz == 12288)   Wc = (const float*)p;
        else if (sz == 192)     bc = (const float*)p;
        else if (sz == 64)      { if (n64 == 0) bn = (const float*)p;
                                  else if (n64 == 1) be = (const float*)p;
                                  else bf = (const float*)p; n64++; }
    }
    float* out = (float*)d_out;

    __half* Wc16_ptr;
    cudaGetSymbolAddress((void**)&Wc16_ptr, d_Wc16);

    hist_kernel<<<(NE + 255) / 256, 256>>>(edst, Wn, We, Wc, Wf);
    scan_kernel<<<NBLK, 256>>>();
    scatter_kernel<<<(NE + 255) / 256, 256>>>(esrc, edst, ef);
    agg_edge_kernel<<<(NN + 7) / 8, 256>>>();
    init_mma_kernel<<<NNPAD / 64, 128>>>(nf, bn, be);
    for (int lv = 0; lv < 3; lv++)
        gather_mma_kernel<<<NN / 16, 512>>>(Wc16_ptr + lv * 4096, bc + lv * 64, lv, bf, gid, out);
}

// round 14
// speedup vs baseline: 1.0605x; 1.0394x over previous
#include <cuda_runtime.h>
#include <cuda_fp16.h>
#include <cstdint>

#define NN 50000
#define NNPAD 50048           // 782 * 64
#define NE 800000
#define NG 128
#define FE 16
#define DD 64
#define NBLK ((NN + 255) / 256)   // 196 scan blocks

// ---------------- scratch (static device globals; no allocation) ----------------
__device__ int    d_counts[NN];          // starts 0; re-zeroed by scan_kernel each run
__device__ int    d_offsets[NN + 1];
__device__ int    d_rank[NE];
__device__ unsigned long long d_scanstate[NBLK];  // starts 0; re-zeroed by scatter_kernel
__device__ int    d_src[NE];             // src node per CSR slot (sorted by dst)
__device__ __half d_ef16p[NE * FE];      // edge features permuted into CSR order, fp16
__device__ float  d_agg16[NNPAD * FE];
__device__ __half d_msg[NNPAD * DD];
__device__ __half d_hA[NNPAD * DD];
__device__ __half d_hB[NNPAD * DD];
__device__ __half d_Wni[80 * 64];        // rows 0-63: W_n2l, rows 64-79: W_e2l
__device__ __half d_Wc16[3 * 64 * 64];
__device__ __half d_Wf16[64 * 64];

__device__ __forceinline__ uint32_t smem_u32(const void* p) {
    return (uint32_t)__cvta_generic_to_shared(p);
}

__device__ __forceinline__ uint32_t h2u(__half2 h) {
    return *reinterpret_cast<uint32_t*>(&h);
}

// ---------------- K1: histogram of edge_dst (rank trick) + fp16 weight conversion ----------------
__global__ void hist_kernel(const int* __restrict__ dst,
                            const float* __restrict__ Wn, const float* __restrict__ We,
                            const float* __restrict__ Wc, const float* __restrict__ Wf) {
    int e = blockIdx.x * blockDim.x + threadIdx.x;
    if (e < NE) d_rank[e] = atomicAdd(&d_counts[dst[e]], 1);
    if (e < 4096) { d_Wni[e] = __float2half(Wn[e]); d_Wf16[e] = __float2half(Wf[e]); }
    else if (e < 5120) d_Wni[e] = __float2half(We[e - 4096]);
    if (e < 12288) d_Wc16[e] = __float2half(Wc[e]);
}

// ---------------- K2: single-pass decoupled-lookback exclusive scan -> offsets; re-zero counts ----------------
__global__ __launch_bounds__(256) void scan_kernel() {
    __shared__ int sm[256];
    __shared__ int s_excl;
    int b = blockIdx.x, t = threadIdx.x;
    int i = b * 256 + t;
    int v = (i < NN) ? d_counts[i] : 0;
    sm[t] = v;
    __syncthreads();
#pragma unroll
    for (int d = 1; d < 256; d <<= 1) {
        int x = (t >= d) ? sm[t - d] : 0;
        __syncthreads();
        sm[t] += x;
        __syncthreads();
    }
    int incl = sm[t];
    int agg = sm[255];
    if (t == 0) {
        unsigned long long fl = (b == 0) ? 2ULL : 1ULL;
        atomicExch(&d_scanstate[b], (fl << 32) | (unsigned long long)(unsigned)agg);
        if (b == 0) s_excl = 0;
    }
    if (b > 0 && t < 32) {
        int lane = t;
        int j = b - 1;
        int excl = 0;
        while (true) {
            int idx = j - lane;
            unsigned long long s;
            if (idx >= 0) {
                do { s = atomicAdd(&d_scanstate[idx], 0ULL); } while ((s >> 32) == 0ULL);
            } else {
                s = (2ULL << 32);
            }
            unsigned fl = (unsigned)(s >> 32);
            int val = (int)(unsigned)(s & 0xffffffffULL);
            unsigned mask = __ballot_sync(0xffffffffu, fl == 2u);
            if (mask) {
                int lmin = __ffs(mask) - 1;
                int contrib = (lane <= lmin) ? val : 0;
#pragma unroll
                for (int o = 16; o > 0; o >>= 1) contrib += __shfl_down_sync(0xffffffffu, contrib, o);
                contrib = __shfl_sync(0xffffffffu, contrib, 0);
                excl += contrib;
                break;
            } else {
                int contrib = val;
#pragma unroll
                for (int o = 16; o > 0; o >>= 1) contrib += __shfl_down_sync(0xffffffffu, contrib, o);
                contrib = __shfl_sync(0xffffffffu, contrib, 0);
                excl += contrib;
                j -= 32;
            }
        }
        if (lane == 0) {
            atomicExch(&d_scanstate[b], (2ULL << 32) | (unsigned long long)(unsigned)(excl + agg));
            s_excl = excl;
        }
    }
    __syncthreads();
    if (i < NN) {
        d_offsets[i] = s_excl + incl - v;
        d_counts[i] = 0;          // restore invariant for next graph replay
    }
    if (b == NBLK - 1 && t == 0) d_offsets[NN] = NE;
}

// ---------------- K3: scatter edges into CSR order + permute edge features to fp16 ----------------
__global__ void scatter_kernel(const int* __restrict__ src, const int* __restrict__ dst,
                               const float* __restrict__ ef) {
    int e = blockIdx.x * blockDim.x + threadIdx.x;
    if (e < NE) {
        int dn = dst[e];
        int p = d_offsets[dn] + d_rank[e];
        d_src[p] = src[e];
        const float4* efr = (const float4*)(ef + e * FE);
        float4 v0 = efr[0], v1 = efr[1], v2 = efr[2], v3 = efr[3];
        uint4 q0 = make_uint4(h2u(__floats2half2_rn(v0.x, v0.y)),
                              h2u(__floats2half2_rn(v0.z, v0.w)),
                              h2u(__floats2half2_rn(v1.x, v1.y)),
                              h2u(__floats2half2_rn(v1.z, v1.w)));
        uint4 q1 = make_uint4(h2u(__floats2half2_rn(v2.x, v2.y)),
                              h2u(__floats2half2_rn(v2.z, v2.w)),
                              h2u(__floats2half2_rn(v3.x, v3.y)),
                              h2u(__floats2half2_rn(v3.z, v3.w)));
        *(uint4*)(d_ef16p + p * FE) = q0;
        *(uint4*)(d_ef16p + p * FE + 8) = q1;
    }
    if (e < NBLK) d_scanstate[e] = 0ULL;   // restore invariant
}

// ---------------- K4a: per-node sum of incident edge features (coalesced CSR walk, R9 form) ----------------
// warp per node; 8 lanes per edge (half2 granularity), 4 edges in flight per warp.
__global__ __launch_bounds__(256) void agg_edge_kernel() {
    int node = blockIdx.x * 8 + (threadIdx.x >> 5);
    if (node >= NN) return;
    int lane = threadIdx.x & 31;
    int f2 = lane & 7;        // half2 index within row (0..7)
    int eg = lane >> 3;       // edge subgroup (0..3)
    int s = d_offsets[node], e = d_offsets[node + 1];
    const __half2* __restrict__ pf = (const __half2*)d_ef16p;
    float2 acc = make_float2(0.f, 0.f);
    for (int base = s; base < e; base += 4) {
        int p = base + eg;
        if (p < e) {
            float2 fv = __half22float2(pf[p * 8 + f2]);
            acc.x += fv.x;
            acc.y += fv.y;
        }
    }
    // reduce across the 4 edge subgroups (lanes differing in bits 3,4)
    acc.x += __shfl_xor_sync(0xffffffffu, acc.x, 8);
    acc.y += __shfl_xor_sync(0xffffffffu, acc.y, 8);
    acc.x += __shfl_xor_sync(0xffffffffu, acc.x, 16);
    acc.y += __shfl_xor_sync(0xffffffffu, acc.y, 16);
    if (lane < 8) *(float2*)(d_agg16 + node * FE + f2 * 2) = acc;
}

// ---------------- K4b: init via HMMA: msg = [nf|agg16] @ [Wn;We] + bn + deg*be ; h0 = relu ----------------
__global__ __launch_bounds__(128) void init_mma_kernel(
    const float* __restrict__ nf, const float* __restrict__ bn, const float* __restrict__ be) {
    __shared__ __half sX[64 * 88];   // 64 rows x 80 cols (stride 88)
    __shared__ __half sW[80 * 88];
    int t = threadIdx.x;
    int blockRow = blockIdx.x * 64;
    for (int idx = t; idx < 64 * 32; idx += 128) {
        int row = idx >> 5, c2 = idx & 31;
        int grow = blockRow + row;
        float2 v = (grow < NN) ? *(const float2*)(nf + grow * 64 + c2 * 2) : make_float2(0.f, 0.f);
        *(__half2*)(sX + row * 88 + c2 * 2) = __floats2half2_rn(v.x, v.y);
    }
    for (int idx = t; idx < 64 * 8; idx += 128) {
        int row = idx >> 3, c2 = idx & 7;
        int grow = blockRow + row;
        float2 v = (grow < NN) ? *(const float2*)(d_agg16 + grow * 16 + c2 * 2) : make_float2(0.f, 0.f);
        *(__half2*)(sX + row * 88 + 64 + c2 * 2) = __floats2half2_rn(v.x, v.y);
    }
    for (int idx = t; idx < 80 * 8; idx += 128) {
        int row = idx >> 3, ch = idx & 7;
        int4 v = *(const int4*)(d_Wni + row * 64 + ch * 8);
        *(int4*)(sW + row * 88 + ch * 8) = v;
    }
    __syncthreads();
    int w = t >> 5, lane = t & 31;
    uint32_t a[5][4];
#pragma unroll
    for (int kk = 0; kk < 5; kk++) {
        uint32_t addr = smem_u32(sX + (w * 16 + (lane & 15)) * 88 + kk * 16 + (lane >> 4) * 8);
        asm volatile("ldmatrix.sync.aligned.m8n8.x4.shared.b16 {%0,%1,%2,%3}, [%4];"
            : "=r"(a[kk][0]), "=r"(a[kk][1]), "=r"(a[kk][2]), "=r"(a[kk][3]) : "r"(addr));
    }
    __half2* msg2 = (__half2*)d_msg;
    __half2* h2 = (__half2*)d_hA;
#pragma unroll
    for (int n = 0; n < 8; n++) {
        float c0 = 0.f, c1 = 0.f, c2 = 0.f, c3 = 0.f;
#pragma unroll
        for (int kk = 0; kk < 5; kk++) {
            uint32_t b0, b1;
            uint32_t addr = smem_u32(sW + (kk * 16 + (lane & 15)) * 88 + n * 8);
            asm volatile("ldmatrix.sync.aligned.m8n8.x2.trans.shared.b16 {%0,%1}, [%2];"
                : "=r"(b0), "=r"(b1) : "r"(addr));
            asm volatile("mma.sync.aligned.m16n8k16.row.col.f32.f16.f16.f32 "
                "{%0,%1,%2,%3}, {%4,%5,%6,%7}, {%8,%9}, {%0,%1,%2,%3};"
                : "+f"(c0), "+f"(c1), "+f"(c2), "+f"(c3)
                : "r"(a[kk][0]), "r"(a[kk][1]), "r"(a[kk][2]), "r"(a[kk][3]), "r"(b0), "r"(b1));
        }
        int r0 = blockRow + w * 16 + (lane >> 2);
        int r1 = r0 + 8;
        int col = n * 8 + (lane & 3) * 2;
        float2 bnv = *(const float2*)(bn + col);
        float2 bev = *(const float2*)(be + col);
        float deg0 = (r0 < NN) ? (float)(d_offsets[r0 + 1] - d_offsets[r0]) : 0.f;
        float deg1 = (r1 < NN) ? (float)(d_offsets[r1 + 1] - d_offsets[r1]) : 0.f;
        float m00 = c0 + bnv.x + deg0 * bev.x;
        float m01 = c1 + bnv.y + deg0 * bev.y;
        float m10 = c2 + bnv.x + deg1 * bev.x;
        float m11 = c3 + bnv.y + deg1 * bev.y;
        msg2[r0 * 32 + (col >> 1)] = __floats2half2_rn(m00, m01);
        msg2[r1 * 32 + (col >> 1)] = __floats2half2_rn(m10, m11);
        h2[r0 * 32 + (col >> 1)] = __floats2half2_rn(fmaxf(m00, 0.f), fmaxf(m01, 0.f));
        h2[r1 * 32 + (col >> 1)] = __floats2half2_rn(fmaxf(m10, 0.f), fmaxf(m11, 0.f));
    }
}

// ---------------- K6: fused gather+GEMM (+ final GEMM & graph-pool on lv2) ----------------
// 512 threads = 16 warps = 16 nodes per block. 50000 = 3125 * 16 exactly.
__global__ __launch_bounds__(512) void gather_mma_kernel(
    const __half* __restrict__ W16, const float* __restrict__ bc, int lv,
    const float* __restrict__ bf, const int* __restrict__ gid, float* __restrict__ out) {
    __shared__ __half sW[64 * 72];
    __shared__ __half sWf[64 * 72];
    __shared__ __half sPool[16 * 72];
    __shared__ __half sH3[16 * 72];
    __shared__ float sOut[16 * 66];
    int t = threadIdx.x;
    int warp = t >> 5, lane = t & 31;
    // zero the output accumulator during lv1 (kernel-boundary-ordered before lv2's atomics)
    if (lv == 1) {
        int gtid = blockIdx.x * 512 + t;
        if (gtid < NG * DD) out[gtid] = 0.f;
    }
    {
        int row = t >> 3, ch = t & 7;
        if (t < 512) {
            *(int4*)(sW + row * 72 + ch * 8) = *(const int4*)(W16 + row * 64 + ch * 8);
            if (lv == 2)
                *(int4*)(sWf + row * 72 + ch * 8) = *(const int4*)(d_Wf16 + row * 64 + ch * 8);
        }
    }
    const __half2* __restrict__ hin = (lv & 1) ? (const __half2*)d_hB : (const __half2*)d_hA;
    __half2* __restrict__ hout = (lv & 1) ? (__half2*)d_hA : (__half2*)d_hB;

    int node = blockIdx.x * 16 + warp;
    int s = d_offsets[node], e = d_offsets[node + 1];
    float2 acc0 = make_float2(0.f, 0.f), acc1 = make_float2(0.f, 0.f);
    float2 acc2 = make_float2(0.f, 0.f), acc3 = make_float2(0.f, 0.f);
    int p = s;
    // 8 rows in flight: hides L2 latency (234-262 cyc) behind MLP
    for (; p + 8 <= e; p += 8) {
        int i0 = d_src[p],     i1 = d_src[p + 1], i2 = d_src[p + 2], i3 = d_src[p + 3];
        int i4 = d_src[p + 4], i5 = d_src[p + 5], i6 = d_src[p + 6], i7 = d_src[p + 7];
        __half2 v0 = hin[i0 * 32 + lane];
        __half2 v1 = hin[i1 * 32 + lane];
        __half2 v2 = hin[i2 * 32 + lane];
        __half2 v3 = hin[i3 * 32 + lane];
        __half2 v4 = hin[i4 * 32 + lane];
        __half2 v5 = hin[i5 * 32 + lane];
        __half2 v6 = hin[i6 * 32 + lane];
        __half2 v7 = hin[i7 * 32 + lane];
        float2 f0 = __half22float2(v0); acc0.x += f0.x; acc0.y += f0.y;
        float2 f1 = __half22float2(v1); acc1.x += f1.x; acc1.y += f1.y;
        float2 f2 = __half22float2(v2); acc2.x += f2.x; acc2.y += f2.y;
        float2 f3 = __half22float2(v3); acc3.x += f3.x; acc3.y += f3.y;
        float2 f4 = __half22float2(v4); acc0.x += f4.x; acc0.y += f4.y;
        float2 f5 = __half22float2(v5); acc1.x += f5.x; acc1.y += f5.y;
        float2 f6 = __half22float2(v6); acc2.x += f6.x; acc2.y += f6.y;
        float2 f7 = __half22float2(v7); acc3.x += f7.x; acc3.y += f7.y;
    }
    for (; p + 4 <= e; p += 4) {
        int i0 = d_src[p], i1 = d_src[p + 1], i2 = d_src[p + 2], i3 = d_src[p + 3];
        float2 f0 = __half22float2(hin[i0 * 32 + lane]);
        float2 f1 = __half22float2(hin[i1 * 32 + lane]);
        float2 f2 = __half22float2(hin[i2 * 32 + lane]);
        float2 f3 = __half22float2(hin[i3 * 32 + lane]);
        acc0.x += f0.x; acc0.y += f0.y;
        acc1.x += f1.x; acc1.y += f1.y;
        acc2.x += f2.x; acc2.y += f2.y;
        acc3.x += f3.x; acc3.y += f3.y;
    }
    for (; p < e; p++) {
        float2 f = __half22float2(hin[d_src[p] * 32 + lane]);
        acc0.x += f.x; acc0.y += f.y;
    }
    float x0 = (acc0.x + acc1.x) + (acc2.x + acc3.x);
    float x1 = (acc0.y + acc1.y) + (acc2.y + acc3.y);
    *(__half2*)(sPool + warp * 72 + 2 * lane) = __floats2half2_rn(x0, x1);
    __syncthreads();

    if (warp < 8) {
        float c0 = 0.f, c1 = 0.f, c2 = 0.f, c3 = 0.f;
#pragma unroll
        for (int kk = 0; kk < 4; kk++) {
            uint32_t a0, a1, a2, a3;
            uint32_t addrA = smem_u32(sPool + (lane & 15) * 72 + kk * 16 + (lane >> 4) * 8);
            asm volatile("ldmatrix.sync.aligned.m8n8.x4.shared.b16 {%0,%1,%2,%3}, [%4];"
                : "=r"(a0), "=r"(a1), "=r"(a2), "=r"(a3) : "r"(addrA));
            uint32_t b0, b1;
            uint32_t addrB = smem_u32(sW + (kk * 16 + (lane & 15)) * 72 + warp * 8);
            asm volatile("ldmatrix.sync.aligned.m8n8.x2.trans.shared.b16 {%0,%1}, [%2];"
                : "=r"(b0), "=r"(b1) : "r"(addrB));
            asm volatile("mma.sync.aligned.m16n8k16.row.col.f32.f16.f16.f32 "
                "{%0,%1,%2,%3}, {%4,%5,%6,%7}, {%8,%9}, {%0,%1,%2,%3};"
                : "+f"(c0), "+f"(c1), "+f"(c2), "+f"(c3)
                : "r"(a0), "r"(a1), "r"(a2), "r"(a3), "r"(b0), "r"(b1));
        }
        int r0 = lane >> 2;
        int col = warp * 8 + (lane & 3) * 2;
        int n0 = blockIdx.x * 16 + r0;
        int n1 = n0 + 8;
        float2 bv = *(const float2*)(bc + col);
        float2 m0 = __half22float2(((const __half2*)d_msg)[n0 * 32 + (col >> 1)]);
        float2 m1 = __half22float2(((const __half2*)d_msg)[n1 * 32 + (col >> 1)]);
        float o00 = fmaxf(c0 + bv.x + m0.x, 0.f);
        float o01 = fmaxf(c1 + bv.y + m0.y, 0.f);
        float o10 = fmaxf(c2 + bv.x + m1.x, 0.f);
        float o11 = fmaxf(c3 + bv.y + m1.y, 0.f);
        if (lv != 2) {
            hout[n0 * 32 + (col >> 1)] = __floats2half2_rn(o00, o01);
            hout[n1 * 32 + (col >> 1)] = __floats2half2_rn(o10, o11);
        } else {
            *(__half2*)(sH3 + r0 * 72 + col) = __floats2half2_rn(o00, o01);
            *(__half2*)(sH3 + (r0 + 8) * 72 + col) = __floats2half2_rn(o10, o11);
        }
    }
    if (lv == 2) {
        __syncthreads();
        // second MMA: y = relu(h3 @ Wf + bf), 16x64 tile
        if (warp < 8) {
            float c0 = 0.f, c1 = 0.f, c2 = 0.f, c3 = 0.f;
#pragma unroll
            for (int kk = 0; kk < 4; kk++) {
                uint32_t a0, a1, a2, a3;
                uint32_t addrA = smem_u32(sH3 + (lane & 15) * 72 + kk * 16 + (lane >> 4) * 8);
                asm volatile("ldmatrix.sync.aligned.m8n8.x4.shared.b16 {%0,%1,%2,%3}, [%4];"
                    : "=r"(a0), "=r"(a1), "=r"(a2), "=r"(a3) : "r"(addrA));
                uint32_t b0, b1;
                uint32_t addrB = smem_u32(sWf + (kk * 16 + (lane & 15)) * 72 + warp * 8);
                asm volatile("ldmatrix.sync.aligned.m8n8.x2.trans.shared.b16 {%0,%1}, [%2];"
                    : "=r"(b0), "=r"(b1) : "r"(addrB));
                asm volatile("mma.sync.aligned.m16n8k16.row.col.f32.f16.f16.f32 "
                    "{%0,%1,%2,%3}, {%4,%5,%6,%7}, {%8,%9}, {%0,%1,%2,%3};"
                    : "+f"(c0), "+f"(c1), "+f"(c2), "+f"(c3)
                    : "r"(a0), "r"(a1), "r"(a2), "r"(a3), "r"(b0), "r"(b1));
            }
            int r0 = lane >> 2;
            int col = warp * 8 + (lane & 3) * 2;
            float2 bv = *(const float2*)(bf + col);
            sOut[r0 * 66 + col]           = fmaxf(c0 + bv.x, 0.f);
            sOut[r0 * 66 + col + 1]       = fmaxf(c1 + bv.y, 0.f);
            sOut[(r0 + 8) * 66 + col]     = fmaxf(c2 + bv.x, 0.f);
            sOut[(r0 + 8) * 66 + col + 1] = fmaxf(c3 + bv.y, 0.f);
        }
        __syncthreads();
        // graph pooling of this block's 16 rows
        if (warp < 2) {
            int colbase = warp * 32 + lane;
            int n0 = blockIdx.x * 16;
            int gv = gid[n0 + (lane & 15)];
            int g0 = __shfl_sync(0xffffffffu, gv, 0);
            bool uni = __all_sync(0xffffffffu, gv == g0);
            if (uni) {
                float sAcc = 0.f;
#pragma unroll
                for (int r = 0; r < 16; r++) sAcc += sOut[r * 66 + colbase];
                atomicAdd(&out[g0 * 64 + colbase], sAcc);
            } else {
                for (int r = 0; r < 16; r++)
                    atomicAdd(&out[gid[n0 + r] * 64 + colbase], sOut[r * 66 + colbase]);
            }
        }
    }
}

// ---------------- host ----------------
extern "C" void kernel_launch(void* const* d_in, const int* in_sizes, int n_in,
                              void* d_out, int out_size) {
    const float *nf = 0, *ef = 0, *Wn = 0, *bn = 0, *We = 0, *be = 0;
    const float *Wc = 0, *bc = 0, *Wf = 0, *bf = 0;
    const int *esrc = 0, *edst = 0, *gid = 0;
    int n800 = 0, n4096 = 0, n64 = 0;
    for (int i = 0; i < n_in; i++) {
        int sz = in_sizes[i];
        const void* p = d_in[i];
        if (sz == NN * 64)      nf = (const float*)p;
        else if (sz == NE * 16) ef = (const float*)p;
        else if (sz == NE)      { if (n800++ == 0) esrc = (const int*)p; else edst = (const int*)p; }
        else if (sz == NN)      gid = (const int*)p;
        else if (sz == 4096)    { if (n4096++ == 0) Wn = (const float*)p; else Wf = (const float*)p; }
        else if (sz == 1024)    We = (const float*)p;
        else if (sz == 12288)   Wc = (const float*)p;
        else if (sz == 192)     bc = (const float*)p;
        else if (sz == 64)      { if (n64 == 0) bn = (const float*)p;
                                  else if (n64 == 1) be = (const float*)p;
                                  else bf = (const float*)p; n64++; }
    }
    float* out = (float*)d_out;

    __half* Wc16_ptr;
    cudaGetSymbolAddress((void**)&Wc16_ptr, d_Wc16);

    hist_kernel<<<(NE + 255) / 256, 256>>>(edst, Wn, We, Wc, Wf);
    scan_kernel<<<NBLK, 256>>>();
    scatter_kernel<<<(NE + 255) / 256, 256>>>(esrc, edst, ef);
    agg_edge_kernel<<<(NN + 7) / 8, 256>>>();
    init_mma_kernel<<<NNPAD / 64, 128>>>(nf, bn, be);
    for (int lv = 0; lv < 3; lv++)
        gather_mma_kernel<<<NN / 16, 512>>>(Wc16_ptr + lv * 4096, bc + lv * 64, lv, bf, gid, out);
}